// round 1
// baseline (speedup 1.0000x reference)
#include <cuda_runtime.h>
#include <math.h>

#define N_PTS 32768
#define DIM   512
#define KCL   1024

#define BM  128   // points per block
#define BK  128   // clusters per K-chunk
#define DC  32    // D-slice per smem stage
#define TPB 256
#define LDT 132   // padded smem stride (128 + 4) -> conflict-free transposed stores

// Scratch (static device arrays: allocation-free)
__device__ float g_xnorm[N_PTS];
__device__ float g_cnorm[KCL];
__device__ float g_ploss[N_PTS];

// ---------------------------------------------------------------------------
// Row squared-norms: one warp per row of 512 floats.
// target = 0 -> g_xnorm, 1 -> g_cnorm
// ---------------------------------------------------------------------------
__global__ void row_norms_kernel(const float* __restrict__ x, int nrows, int target) {
    int warp = (blockIdx.x * blockDim.x + threadIdx.x) >> 5;
    int lane = threadIdx.x & 31;
    if (warp >= nrows) return;
    const float4* row = reinterpret_cast<const float4*>(x + (size_t)warp * DIM);
    float s = 0.f;
    #pragma unroll
    for (int i = 0; i < (DIM / 4) / 32; i++) {   // 128 float4 / 32 lanes = 4
        float4 v = row[lane + 32 * i];
        s = fmaf(v.x, v.x, s);
        s = fmaf(v.y, v.y, s);
        s = fmaf(v.z, v.z, s);
        s = fmaf(v.w, v.w, s);
    }
    #pragma unroll
    for (int o = 16; o > 0; o >>= 1) s += __shfl_xor_sync(0xffffffffu, s, o);
    if (lane == 0) {
        if (target) g_cnorm[warp] = s;
        else        g_xnorm[warp] = s;
    }
}

// ---------------------------------------------------------------------------
// Main fused kernel: distances + online softmax + argmin + centroid gather.
// Grid: N_PTS / BM = 256 blocks, 256 threads.
// Thread (ty, tx) = (tid/16, tid%16): 8 points (ty*8+p), 8 clusters (tx+16j).
// ---------------------------------------------------------------------------
__global__ __launch_bounds__(TPB, 1)
void dkm_main_kernel(const float* __restrict__ input,
                     const float* __restrict__ crep,
                     float* __restrict__ out_centroids,   // [N_PTS * DIM]
                     float* __restrict__ out_idx)         // [N_PTS] as float
{
    __shared__ float As[DC][LDT];   // [d][point]
    __shared__ float Bs[DC][LDT];   // [d][cluster]
    __shared__ float s_xn[BM];
    __shared__ float s_cn[BK];
    __shared__ int   s_idx[BM];

    const int tid  = threadIdx.x;
    const int tx   = tid & 15;
    const int ty   = tid >> 4;
    const int row0 = blockIdx.x * BM;

    if (tid < BM) s_xn[tid] = g_xnorm[row0 + tid];

    // per-point online softmax state (8 points per thread)
    float m[8], l[8], s[8];
    int   bidx[8];
    #pragma unroll
    for (int p = 0; p < 8; p++) { m[p] = 3.4e38f; l[p] = 0.f; s[p] = 0.f; bidx[p] = 0; }

    for (int k0 = 0; k0 < KCL; k0 += BK) {
        __syncthreads();                       // protect s_cn from prior-chunk readers
        if (tid < BK) s_cn[tid] = g_cnorm[k0 + tid];

        float acc[8][8];
        #pragma unroll
        for (int p = 0; p < 8; p++)
            #pragma unroll
            for (int j = 0; j < 8; j++) acc[p][j] = 0.f;

        for (int d0 = 0; d0 < DIM; d0 += DC) {
            __syncthreads();
            // Stage A tile (128 pts x 32 d) and B tile (128 clusters x 32 d),
            // stored transposed [d][col]; pad-4 stride keeps STS conflict-free.
            #pragma unroll
            for (int i = 0; i < 4; i++) {
                int e  = (tid + i * TPB) * 4;       // element idx, point-major
                int p  = e >> 5;                    // /DC
                int dd = e & 31;
                float4 v = *reinterpret_cast<const float4*>(
                    &input[(size_t)(row0 + p) * DIM + d0 + dd]);
                As[dd + 0][p] = v.x; As[dd + 1][p] = v.y;
                As[dd + 2][p] = v.z; As[dd + 3][p] = v.w;
            }
            #pragma unroll
            for (int i = 0; i < 4; i++) {
                int e  = (tid + i * TPB) * 4;
                int c  = e >> 5;
                int dd = e & 31;
                float4 v = *reinterpret_cast<const float4*>(
                    &crep[(size_t)(k0 + c) * DIM + d0 + dd]);
                Bs[dd + 0][c] = v.x; Bs[dd + 1][c] = v.y;
                Bs[dd + 2][c] = v.z; Bs[dd + 3][c] = v.w;
            }
            __syncthreads();

            #pragma unroll
            for (int d = 0; d < DC; d++) {
                float a[8], b[8];
                float4 a0 = *reinterpret_cast<const float4*>(&As[d][ty * 8]);
                float4 a1 = *reinterpret_cast<const float4*>(&As[d][ty * 8 + 4]);
                a[0] = a0.x; a[1] = a0.y; a[2] = a0.z; a[3] = a0.w;
                a[4] = a1.x; a[5] = a1.y; a[6] = a1.z; a[7] = a1.w;
                #pragma unroll
                for (int j = 0; j < 8; j++) b[j] = Bs[d][tx + 16 * j];  // strided: bank-clean
                #pragma unroll
                for (int p = 0; p < 8; p++)
                    #pragma unroll
                    for (int j = 0; j < 8; j++)
                        acc[p][j] = fmaf(a[p], b[j], acc[p][j]);
            }
        }

        // Online softmax / argmin update for this K-chunk.
        #pragma unroll
        for (int p = 0; p < 8; p++) {
            float xn = s_xn[ty * 8 + p];
            float d2v[8];
            float lmin = 3.4e38f;
            int   larg = 0;
            #pragma unroll
            for (int j = 0; j < 8; j++) {
                float d2 = xn + s_cn[tx + 16 * j] - 2.0f * acc[p][j];
                d2v[j] = d2;
                if (d2 < lmin) { lmin = d2; larg = k0 + tx + 16 * j; }
            }
            float newm = fminf(m[p], lmin);
            if (lmin < m[p]) bidx[p] = larg;
            float sc = __expf(newm - m[p]);      // <= 1; first chunk: exp(-huge)=0, l=s=0 anyway
            l[p] *= sc;
            s[p] *= sc;
            #pragma unroll
            for (int j = 0; j < 8; j++) {
                float w = __expf(newm - d2v[j]); // arg <= 0, no overflow
                l[p] += w;
                s[p] = fmaf(w, d2v[j], s[p]);
            }
            m[p] = newm;
        }
    }

    // Cross-thread merge across the 16 tx lanes (width-16 shuffle segments).
    #pragma unroll
    for (int p = 0; p < 8; p++) {
        #pragma unroll
        for (int o = 8; o > 0; o >>= 1) {
            float m2 = __shfl_xor_sync(0xffffffffu, m[p], o, 16);
            float l2 = __shfl_xor_sync(0xffffffffu, l[p], o, 16);
            float s2 = __shfl_xor_sync(0xffffffffu, s[p], o, 16);
            int   i2 = __shfl_xor_sync(0xffffffffu, bidx[p], o, 16);
            float M = fminf(m[p], m2);
            if (m2 < m[p] || (m2 == m[p] && i2 < bidx[p])) bidx[p] = i2;
            float sc1 = __expf(M - m[p]);
            float sc2 = __expf(M - m2);
            l[p] = l[p] * sc1 + l2 * sc2;
            s[p] = s[p] * sc1 + s2 * sc2;
            m[p] = M;
        }
    }

    if (tx == 0) {
        #pragma unroll
        for (int p = 0; p < 8; p++) {
            int n = row0 + ty * 8 + p;
            out_idx[n]        = (float)bidx[p];
            g_ploss[n]        = s[p] / l[p];
            s_idx[ty * 8 + p] = bidx[p];
        }
    }
    __syncthreads();

    // Fused centroid gather: cluster table is L2-resident (2 MB).
    for (int i = tid; i < BM * (DIM / 4); i += TPB) {
        int p  = i >> 7;            // DIM/4 = 128 float4 per row
        int c4 = i & 127;
        int ci = s_idx[p];
        float4 v = *reinterpret_cast<const float4*>(&crep[(size_t)ci * DIM + c4 * 4]);
        *reinterpret_cast<float4*>(&out_centroids[(size_t)(row0 + p) * DIM + c4 * 4]) = v;
    }
}

// ---------------------------------------------------------------------------
// Deterministic loss reduction: fixed-order strided partials + shared tree.
// ---------------------------------------------------------------------------
__global__ void loss_reduce_kernel(float* __restrict__ out_loss) {
    __shared__ float sm[1024];
    int tid = threadIdx.x;
    float acc = 0.f;
    for (int i = tid; i < N_PTS; i += 1024) acc += g_ploss[i];
    sm[tid] = acc;
    __syncthreads();
    #pragma unroll
    for (int o = 512; o > 0; o >>= 1) {
        if (tid < o) sm[tid] += sm[tid + o];
        __syncthreads();
    }
    if (tid == 0) out_loss[0] = sm[0] * (1.0f / (float)KCL);
}

// ---------------------------------------------------------------------------
extern "C" void kernel_launch(void* const* d_in, const int* in_sizes, int n_in,
                              void* d_out, int out_size) {
    const float* input = (const float*)d_in[0];   // [N, D]
    const float* crep  = (const float*)d_in[1];   // [K, D]

    float* out           = (float*)d_out;
    float* out_centroids = out;                                    // N*D
    float* out_idx       = out + (size_t)N_PTS * DIM;              // N
    float* out_loss      = out + (size_t)N_PTS * DIM + N_PTS;      // 1

    // 1) row norms (warp per row)
    {
        int warps  = N_PTS;
        int blocks = (warps * 32 + TPB - 1) / TPB;
        row_norms_kernel<<<blocks, TPB>>>(input, N_PTS, 0);
    }
    {
        int warps  = KCL;
        int blocks = (warps * 32 + TPB - 1) / TPB;
        row_norms_kernel<<<blocks, TPB>>>(crep, KCL, 1);
    }

    // 2) fused distances + softmax + argmin + gather
    dkm_main_kernel<<<N_PTS / BM, TPB>>>(input, crep, out_centroids, out_idx);

    // 3) deterministic loss reduction
    loss_reduce_kernel<<<1, 1024>>>(out_loss);
}

// round 3
// speedup vs baseline: 1.4375x; 1.4375x over previous
#include <cuda_runtime.h>
#include <stdint.h>
#include <math.h>

#define N_PTS 32768
#define DIM   512
#define KCL   1024

// ---------------- scratch (static device arrays: allocation-free) ----------
__device__ float g_Ah[(size_t)N_PTS * DIM];   // 64 MB  tf32-rounded hi
__device__ float g_Al[(size_t)N_PTS * DIM];   // 64 MB  tf32-rounded lo
__device__ float g_Bh[(size_t)KCL * DIM];     // 2 MB
__device__ float g_Bl[(size_t)KCL * DIM];     // 2 MB
__device__ float g_xnorm[N_PTS];
__device__ float g_cnorm[KCL];
__device__ float g_ploss[N_PTS];

__device__ __forceinline__ float to_tf32(float x) {
    uint32_t r;
    asm("cvt.rna.tf32.f32 %0, %1;" : "=r"(r) : "f"(x));
    return __uint_as_float(r);
}

// m16n8k8 tf32 MMA, D=C accumulate in fp32
#define MMA_TF32(d, a, b)                                                       \
    asm volatile(                                                               \
        "mma.sync.aligned.m16n8k8.row.col.f32.tf32.tf32.f32 "                   \
        "{%0,%1,%2,%3},{%4,%5,%6,%7},{%8,%9},{%0,%1,%2,%3};"                    \
        : "+f"((d)[0]), "+f"((d)[1]), "+f"((d)[2]), "+f"((d)[3])                \
        : "r"((a)[0]), "r"((a)[1]), "r"((a)[2]), "r"((a)[3]),                   \
          "r"((b)[0]), "r"((b)[1]))

#define CP_ASYNC16(dst, src)                                                    \
    asm volatile("cp.async.cg.shared.global [%0], [%1], 16;"                    \
                 :: "r"(dst), "l"(src) : "memory")
#define CP_COMMIT()  asm volatile("cp.async.commit_group;" ::: "memory")
#define CP_WAIT(n)   asm volatile("cp.async.wait_group %0;" :: "n"(n) : "memory")

__device__ __forceinline__ uint32_t smem_u32(const void* p) {
    uint32_t a;
    asm("{ .reg .u64 t; cvta.to.shared.u64 t, %1; cvt.u32.u64 %0, t; }" : "=r"(a) : "l"(p));
    return a;
}

// ---------------------------------------------------------------------------
// Convert fp32 rows -> tf32 (hi, lo) split + squared norms. One warp per row.
// ---------------------------------------------------------------------------
__global__ void convert_tf32_kernel(const float* __restrict__ x,
                                    float* __restrict__ hi_arr,
                                    float* __restrict__ lo_arr,
                                    float* __restrict__ norm_arr,
                                    int nrows) {
    int warp = (blockIdx.x * blockDim.x + threadIdx.x) >> 5;
    int lane = threadIdx.x & 31;
    if (warp >= nrows) return;
    const float* row = x + (size_t)warp * DIM;
    float* hrow = hi_arr + (size_t)warp * DIM;
    float* lrow = lo_arr + (size_t)warp * DIM;
    float sq = 0.f;
    #pragma unroll
    for (int i = 0; i < 4; i++) {
        int d = i * 128 + lane * 4;
        float4 v = *reinterpret_cast<const float4*>(row + d);
        float vv[4] = {v.x, v.y, v.z, v.w};
        float hv[4], lv[4];
        #pragma unroll
        for (int q = 0; q < 4; q++) {
            float val = vv[q];
            sq = fmaf(val, val, sq);
            hv[q] = to_tf32(val);
            lv[q] = to_tf32(val - hv[q]);
        }
        *reinterpret_cast<float4*>(hrow + d) = make_float4(hv[0], hv[1], hv[2], hv[3]);
        *reinterpret_cast<float4*>(lrow + d) = make_float4(lv[0], lv[1], lv[2], lv[3]);
    }
    #pragma unroll
    for (int o = 16; o > 0; o >>= 1) sq += __shfl_xor_sync(0xffffffffu, sq, o);
    if (lane == 0) norm_arr[warp] = sq;
}

// ---------------------------------------------------------------------------
// Main kernel: 3xTF32 mma.sync GEMM + fused softmax/argmin/gather.
// CTA: 256 threads (8 warps of 64x64), tile M=128, N-chunks of 256 (x4).
// K stages of 16 tf32; smem stage = Ah|Al|Bh|Bl with stride-20 padded rows.
// ---------------------------------------------------------------------------
#define STG_A   10240              // 128 rows * 80B
#define STG_B   20480              // 256 rows * 80B
#define STG_SZ  (2*STG_A + 2*STG_B)   // 61440
#define NSTG    128                // 4 chunks * 32 k-steps
#define DSMEM   (2 * STG_SZ)       // 122880

__global__ __launch_bounds__(256, 1)
void dkm_gemm_kernel(const float* __restrict__ crep,
                     float* __restrict__ out_centroids,
                     float* __restrict__ out_idx)
{
    extern __shared__ __align__(128) char dsm[];
    __shared__ float s_cn[KCL];
    __shared__ float s_xn[128];
    __shared__ float s_pm[4][128], s_pl[4][128], s_ps[4][128];
    __shared__ int   s_pi[4][128], s_idx[128];

    const int tid  = threadIdx.x;
    const int wid  = tid >> 5;
    const int lane = tid & 31;
    const int q    = lane >> 2;
    const int kl   = lane & 3;
    const int wm   = wid & 1;          // M-tile (0..1)
    const int wn   = wid >> 1;         // N-tile (0..3)
    const int row0 = blockIdx.x * 128;

    for (int i = tid; i < KCL; i += 256) s_cn[i] = g_cnorm[i];
    if (tid < 128) s_xn[tid] = g_xnorm[row0 + tid];
    __syncthreads();

    // ---- stage loader: 3072 x 16B chunks, 12 per thread -------------------
    auto load_stage = [&](int s) {
        const int nc = s >> 5, ks = s & 31;
        const int k0 = ks * 16, c0 = nc * 256;
        const uint32_t base = smem_u32(dsm) + (s & 1) * STG_SZ;
        #pragma unroll
        for (int it = 0; it < 12; it++) {
            int i = it * 256 + tid;
            uint32_t dst; const float* src;
            if (i < 1024) {                       // A tiles (hi, lo)
                int sec = i >> 9, j = i & 511;
                int r = j >> 2, u = j & 3;
                src = (sec ? g_Al : g_Ah) + (size_t)(row0 + r) * DIM + k0 + u * 4;
                dst = base + sec * STG_A + r * 80 + u * 16;
            } else {                              // B tiles (hi, lo)
                int i2 = i - 1024;
                int sec = i2 >> 10, j = i2 & 1023;
                int r = j >> 2, u = j & 3;
                src = (sec ? g_Bl : g_Bh) + (size_t)(c0 + r) * DIM + k0 + u * 4;
                dst = base + 2 * STG_A + sec * STG_B + r * 80 + u * 16;
            }
            CP_ASYNC16(dst, src);
        }
        CP_COMMIT();
    };

    // ---- per-point running softmax state (8 points per lane) --------------
    float rm[8], rl[8], rs[8];
    int   ri[8];
    #pragma unroll
    for (int p = 0; p < 8; p++) { rm[p] = 3.4e38f; rl[p] = 0.f; rs[p] = 0.f; ri[p] = 0; }

    float acc[4][8][4];
    #pragma unroll
    for (int mf = 0; mf < 4; mf++)
        #pragma unroll
        for (int nf = 0; nf < 8; nf++)
            #pragma unroll
            for (int t = 0; t < 4; t++) acc[mf][nf][t] = 0.f;

    load_stage(0);

    for (int s = 0; s < NSTG; s++) {
        if (s + 1 < NSTG) load_stage(s + 1);
        if (s + 1 < NSTG) { CP_WAIT(1); } else { CP_WAIT(0); }
        __syncthreads();

        const char* stg = dsm + (s & 1) * STG_SZ;
        const uint32_t* Ah_s = (const uint32_t*)(stg);
        const uint32_t* Al_s = (const uint32_t*)(stg + STG_A);
        const uint32_t* Bh_s = (const uint32_t*)(stg + 2 * STG_A);
        const uint32_t* Bl_s = (const uint32_t*)(stg + 2 * STG_A + STG_B);

        #pragma unroll
        for (int k8 = 0; k8 < 2; k8++) {
            const int kb = k8 * 8;
            uint32_t ah[4][4], al[4][4], bb[8][2];
            #pragma unroll
            for (int mf = 0; mf < 4; mf++) {
                int ra = (wm * 64 + mf * 16 + q) * 20;
                ah[mf][0] = Ah_s[ra + kb + kl];
                ah[mf][1] = Ah_s[ra + 160 + kb + kl];
                ah[mf][2] = Ah_s[ra + kb + 4 + kl];
                ah[mf][3] = Ah_s[ra + 160 + kb + 4 + kl];
                al[mf][0] = Al_s[ra + kb + kl];
                al[mf][1] = Al_s[ra + 160 + kb + kl];
                al[mf][2] = Al_s[ra + kb + 4 + kl];
                al[mf][3] = Al_s[ra + 160 + kb + 4 + kl];
            }
            #pragma unroll
            for (int nf = 0; nf < 8; nf++) {
                int cb = (wn * 64 + nf * 8 + q) * 20;
                bb[nf][0] = Bh_s[cb + kb + kl];
                bb[nf][1] = Bh_s[cb + kb + 4 + kl];
            }
            #pragma unroll
            for (int mf = 0; mf < 4; mf++)
                #pragma unroll
                for (int nf = 0; nf < 8; nf++) MMA_TF32(acc[mf][nf], ah[mf], bb[nf]);
            #pragma unroll
            for (int mf = 0; mf < 4; mf++)
                #pragma unroll
                for (int nf = 0; nf < 8; nf++) MMA_TF32(acc[mf][nf], al[mf], bb[nf]);
            #pragma unroll
            for (int nf = 0; nf < 8; nf++) {
                int cb = (wn * 64 + nf * 8 + q) * 20;
                bb[nf][0] = Bl_s[cb + kb + kl];
                bb[nf][1] = Bl_s[cb + kb + 4 + kl];
            }
            #pragma unroll
            for (int mf = 0; mf < 4; mf++)
                #pragma unroll
                for (int nf = 0; nf < 8; nf++) MMA_TF32(acc[mf][nf], ah[mf], bb[nf]);
        }

        // ---- chunk boundary: online softmax/argmin epilogue ---------------
        if ((s & 31) == 31) {
            const int nc = s >> 5;
            #pragma unroll
            for (int mf = 0; mf < 4; mf++) {
                #pragma unroll
                for (int j = 0; j < 2; j++) {
                    const int p   = mf * 2 + j;
                    const int rloc = wm * 64 + mf * 16 + j * 8 + q;
                    const float xn = s_xn[rloc];
                    float d2v[16];
                    float bm = 3.4e38f; int ba = 0;
                    #pragma unroll
                    for (int nf = 0; nf < 8; nf++) {
                        #pragma unroll
                        for (int t = 0; t < 2; t++) {
                            int col = nc * 256 + wn * 64 + nf * 8 + 2 * kl + t;
                            float d2 = xn + s_cn[col] - 2.f * acc[mf][nf][j * 2 + t];
                            d2v[nf * 2 + t] = d2;
                            if (d2 < bm || (d2 == bm && col < ba)) { bm = d2; ba = col; }
                        }
                    }
                    // quad reduce (min, argmin)
                    #pragma unroll
                    for (int o = 1; o <= 2; o <<= 1) {
                        float om = __shfl_xor_sync(0xffffffffu, bm, o);
                        int   oa = __shfl_xor_sync(0xffffffffu, ba, o);
                        if (om < bm || (om == bm && oa < ba)) { bm = om; ba = oa; }
                    }
                    // local exp sums vs chunk max bm
                    float le = 0.f, se = 0.f;
                    #pragma unroll
                    for (int v = 0; v < 16; v++) {
                        float w = __expf(bm - d2v[v]);
                        le += w;
                        se = fmaf(w, d2v[v], se);
                    }
                    #pragma unroll
                    for (int o = 1; o <= 2; o <<= 1) {
                        le += __shfl_xor_sync(0xffffffffu, le, o);
                        se += __shfl_xor_sync(0xffffffffu, se, o);
                    }
                    // merge into running
                    float newm = fminf(rm[p], bm);
                    if (bm < rm[p] || (bm == rm[p] && ba < ri[p])) ri[p] = ba;
                    float sc_old = __expf(newm - rm[p]);
                    float sc_new = __expf(newm - bm);
                    rl[p] = rl[p] * sc_old + le * sc_new;
                    rs[p] = rs[p] * sc_old + se * sc_new;
                    rm[p] = newm;
                    // zero accums for next chunk
                    #pragma unroll
                    for (int nf = 0; nf < 8; nf++) {
                        acc[mf][nf][j * 2 + 0] = 0.f;
                        acc[mf][nf][j * 2 + 1] = 0.f;
                    }
                }
            }
        }
        __syncthreads();
    }

    // ---- write per-warp partials (one lane per quad) ----------------------
    if (kl == 0) {
        #pragma unroll
        for (int mf = 0; mf < 4; mf++) {
            #pragma unroll
            for (int j = 0; j < 2; j++) {
                int p = mf * 2 + j;
                int rloc = wm * 64 + mf * 16 + j * 8 + q;
                s_pm[wn][rloc] = rm[p];
                s_pl[wn][rloc] = rl[p];
                s_ps[wn][rloc] = rs[p];
                s_pi[wn][rloc] = ri[p];
            }
        }
    }
    __syncthreads();

    // ---- final per-point merge over the 4 N-tile warps --------------------
    if (tid < 128) {
        float m = s_pm[0][tid]; int bi = s_pi[0][tid];
        #pragma unroll
        for (int w = 1; w < 4; w++) {
            float om = s_pm[w][tid]; int oi = s_pi[w][tid];
            if (om < m || (om == m && oi < bi)) { m = om; bi = oi; }
        }
        float l = 0.f, ssum = 0.f;
        #pragma unroll
        for (int w = 0; w < 4; w++) {
            float sc = __expf(m - s_pm[w][tid]);
            l    += s_pl[w][tid] * sc;
            ssum += s_ps[w][tid] * sc;
        }
        int n = row0 + tid;
        out_idx[n] = (float)bi;
        g_ploss[n] = ssum / l;
        s_idx[tid] = bi;
    }
    __syncthreads();

    // ---- fused centroid gather (cluster table L2-resident) ----------------
    for (int i = tid; i < 128 * (DIM / 4); i += 256) {
        int p = i >> 7, c4 = i & 127;
        int ci = s_idx[p];
        float4 v = *reinterpret_cast<const float4*>(crep + (size_t)ci * DIM + c4 * 4);
        *reinterpret_cast<float4*>(out_centroids + (size_t)(row0 + p) * DIM + c4 * 4) = v;
    }
}

// ---------------------------------------------------------------------------
__global__ void loss_reduce_kernel(float* __restrict__ out_loss) {
    __shared__ float sm[1024];
    int tid = threadIdx.x;
    float acc = 0.f;
    for (int i = tid; i < N_PTS; i += 1024) acc += g_ploss[i];
    sm[tid] = acc;
    __syncthreads();
    #pragma unroll
    for (int o = 512; o > 0; o >>= 1) {
        if (tid < o) sm[tid] += sm[tid + o];
        __syncthreads();
    }
    if (tid == 0) out_loss[0] = sm[0] * (1.0f / (float)KCL);
}

// ---------------------------------------------------------------------------
extern "C" void kernel_launch(void* const* d_in, const int* in_sizes, int n_in,
                              void* d_out, int out_size) {
    const float* input = (const float*)d_in[0];   // [N, D]
    const float* crep  = (const float*)d_in[1];   // [K, D]

    float* out           = (float*)d_out;
    float* out_centroids = out;
    float* out_idx       = out + (size_t)N_PTS * DIM;
    float* out_loss      = out + (size_t)N_PTS * DIM + N_PTS;

    float *Ah, *Al, *Bh, *Bl, *xn, *cn;
    cudaGetSymbolAddress((void**)&Ah, g_Ah);
    cudaGetSymbolAddress((void**)&Al, g_Al);
    cudaGetSymbolAddress((void**)&Bh, g_Bh);
    cudaGetSymbolAddress((void**)&Bl, g_Bl);
    cudaGetSymbolAddress((void**)&xn, g_xnorm);
    cudaGetSymbolAddress((void**)&cn, g_cnorm);

    convert_tf32_kernel<<<(N_PTS * 32) / 256, 256>>>(input, Ah, Al, xn, N_PTS);
    convert_tf32_kernel<<<(KCL * 32) / 256, 256>>>(crep, Bh, Bl, cn, KCL);

    cudaFuncSetAttribute(dkm_gemm_kernel, cudaFuncAttributeMaxDynamicSharedMemorySize, DSMEM);
    dkm_gemm_kernel<<<N_PTS / 128, 256, DSMEM>>>(crep, out_centroids, out_idx);

    loss_reduce_kernel<<<1, 1024>>>(out_loss);
}

// round 4
// speedup vs baseline: 2.4171x; 1.6814x over previous
#include <cuda_runtime.h>
#include <cuda_fp16.h>
#include <stdint.h>
#include <math.h>

#define N_PTS 32768
#define DIM   512
#define KCL   1024

// ---------------- scratch (static device arrays: allocation-free) ----------
__device__ __half g_Ah[(size_t)N_PTS * DIM];   // 32 MB  fp16 hi
__device__ __half g_Al[(size_t)N_PTS * DIM];   // 32 MB  fp16 lo (residual)
__device__ __half g_Bh[(size_t)KCL * DIM];     // 1 MB
__device__ __half g_Bl[(size_t)KCL * DIM];     // 1 MB
__device__ float g_xnorm[N_PTS];
__device__ float g_cnorm[KCL];
__device__ float g_ploss[N_PTS];

// m16n8k16 fp16 MMA, fp32 accumulate, D=C
#define MMA_F16(d, a, b)                                                        \
    asm volatile(                                                               \
        "mma.sync.aligned.m16n8k16.row.col.f32.f16.f16.f32 "                    \
        "{%0,%1,%2,%3},{%4,%5,%6,%7},{%8,%9},{%0,%1,%2,%3};"                    \
        : "+f"((d)[0]), "+f"((d)[1]), "+f"((d)[2]), "+f"((d)[3])                \
        : "r"((a)[0]), "r"((a)[1]), "r"((a)[2]), "r"((a)[3]),                   \
          "r"((b)[0]), "r"((b)[1]))

#define CP_ASYNC16(dst, src)                                                    \
    asm volatile("cp.async.cg.shared.global [%0], [%1], 16;"                    \
                 :: "r"(dst), "l"(src) : "memory")
#define CP_COMMIT()  asm volatile("cp.async.commit_group;" ::: "memory")
#define CP_WAIT(n)   asm volatile("cp.async.wait_group %0;" :: "n"(n) : "memory")

#define SWZ(x) ((x) ^ (((x) >> 3) & 0x70))

__device__ __forceinline__ uint32_t smem_u32(const void* p) {
    uint32_t a;
    asm("{ .reg .u64 t; cvta.to.shared.u64 t, %1; cvt.u32.u64 %0, t; }" : "=r"(a) : "l"(p));
    return a;
}

// ---------------------------------------------------------------------------
// Convert fp32 rows -> fp16 (hi, lo) split + squared norms. One warp per row.
// ---------------------------------------------------------------------------
__global__ void convert_f16_kernel(const float* __restrict__ x,
                                   __half* __restrict__ hi_arr,
                                   __half* __restrict__ lo_arr,
                                   float* __restrict__ norm_arr,
                                   int nrows) {
    int warp = (blockIdx.x * blockDim.x + threadIdx.x) >> 5;
    int lane = threadIdx.x & 31;
    if (warp >= nrows) return;
    const float* row = x + (size_t)warp * DIM;
    __half* hrow = hi_arr + (size_t)warp * DIM;
    __half* lrow = lo_arr + (size_t)warp * DIM;
    float sq = 0.f;
    #pragma unroll
    for (int i = 0; i < 4; i++) {
        int d = i * 128 + lane * 4;
        float4 v = *reinterpret_cast<const float4*>(row + d);
        float vv[4] = {v.x, v.y, v.z, v.w};
        __half hv[4], lv[4];
        #pragma unroll
        for (int q = 0; q < 4; q++) {
            float val = vv[q];
            sq = fmaf(val, val, sq);
            hv[q] = __float2half_rn(val);
            lv[q] = __float2half_rn(val - __half2float(hv[q]));
        }
        *reinterpret_cast<uint2*>(hrow + d) = *reinterpret_cast<uint2*>(hv);
        *reinterpret_cast<uint2*>(lrow + d) = *reinterpret_cast<uint2*>(lv);
    }
    #pragma unroll
    for (int o = 16; o > 0; o >>= 1) sq += __shfl_xor_sync(0xffffffffu, sq, o);
    if (lane == 0) norm_arr[warp] = sq;
}

// ---------------------------------------------------------------------------
// Main kernel: 4xFP16 mma.sync GEMM + fused softmax/argmin/gather.
// CTA: 256 threads (8 warps of 64x64), tile M=128, N-chunks of 256 (x4).
// Stage = k32 halves; rows are [hi 64B | lo 64B] = 128B, SW128 swizzled.
// ---------------------------------------------------------------------------
#define STG_A   16384              // 128 rows * 128B
#define STG_B   32768              // 256 rows * 128B
#define STG_SZ  (STG_A + STG_B)    // 49152
#define NSTG    64                 // 4 chunks * 16 k-steps (k32 each)
#define DSMEM   (2 * STG_SZ)       // 98304

__global__ __launch_bounds__(256, 1)
void dkm_gemm_kernel(const float* __restrict__ crep,
                     float* __restrict__ out_centroids,
                     float* __restrict__ out_idx)
{
    extern __shared__ __align__(128) char dsm[];
    __shared__ float s_cn[KCL];
    __shared__ float s_xn[128];
    __shared__ float s_pm[4][128], s_pl[4][128], s_ps[4][128];
    __shared__ int   s_pi[4][128], s_idx[128];

    const int tid  = threadIdx.x;
    const int wid  = tid >> 5;
    const int lane = tid & 31;
    const int q    = lane >> 2;
    const int kl   = lane & 3;
    const int wm   = wid & 1;          // M-tile (0..1)
    const int wn   = wid >> 1;         // N-tile (0..3)
    const int row0 = blockIdx.x * 128;

    for (int i = tid; i < KCL; i += 256) s_cn[i] = g_cnorm[i];
    if (tid < 128) s_xn[tid] = g_xnorm[row0 + tid];
    __syncthreads();

    // ---- stage loader: 3072 x 16B chunks, 12 per thread -------------------
    auto load_stage = [&](int s) {
        const int nc = s >> 4, ks = s & 15;
        const int k0 = ks * 32, c0 = nc * 256;
        const uint32_t base = smem_u32(dsm) + (s & 1) * STG_SZ;
        #pragma unroll
        for (int it = 0; it < 12; it++) {
            int i = it * 256 + tid;
            uint32_t dst; const __half* src;
            if (i < 1024) {                       // A: 128 rows x 8 chunks
                int r = i >> 3, c = i & 7;
                src = (c < 4 ? g_Ah + (size_t)(row0 + r) * DIM + k0 + c * 8
                             : g_Al + (size_t)(row0 + r) * DIM + k0 + (c - 4) * 8);
                dst = base + SWZ((uint32_t)(r * 128 + c * 16));
            } else {                              // B: 256 rows x 8 chunks
                int j = i - 1024, r = j >> 3, c = j & 7;
                src = (c < 4 ? g_Bh + (size_t)(c0 + r) * DIM + k0 + c * 8
                             : g_Bl + (size_t)(c0 + r) * DIM + k0 + (c - 4) * 8);
                dst = base + STG_A + SWZ((uint32_t)(r * 128 + c * 16));
            }
            CP_ASYNC16(dst, (const void*)src);
        }
        CP_COMMIT();
    };

    // ---- per-point running softmax state (8 points per lane) --------------
    float rm[8], rl[8], rs[8];
    int   ri[8];
    #pragma unroll
    for (int p = 0; p < 8; p++) { rm[p] = 3.4e38f; rl[p] = 0.f; rs[p] = 0.f; ri[p] = 0; }

    float acc[4][8][4];
    #pragma unroll
    for (int mf = 0; mf < 4; mf++)
        #pragma unroll
        for (int nf = 0; nf < 8; nf++)
            #pragma unroll
            for (int t = 0; t < 4; t++) acc[mf][nf][t] = 0.f;

    load_stage(0);

    for (int s = 0; s < NSTG; s++) {
        if (s + 1 < NSTG) load_stage(s + 1);
        if (s + 1 < NSTG) { CP_WAIT(1); } else { CP_WAIT(0); }
        __syncthreads();

        const char* stgA = dsm + (s & 1) * STG_SZ;
        const char* stgB = stgA + STG_A;

        #pragma unroll
        for (int kb = 0; kb < 2; kb++) {           // two k16 steps per stage
            const uint32_t kbb = kb * 32;          // byte offset of k16 block
            uint32_t ah[4][4], am[4][4], bh[8][2], bm[8][2];
            #pragma unroll
            for (int mf = 0; mf < 4; mf++) {
                const int r = wm * 64 + mf * 16 + q;
                const uint32_t sw = (uint32_t)((r & 7) << 4);
                const char* p0 = stgA + r * 128;
                const char* p1 = stgA + (r + 8) * 128;
                ah[mf][0] = *(const uint32_t*)(p0 + ((kbb      + kl * 4) ^ sw));
                ah[mf][1] = *(const uint32_t*)(p1 + ((kbb      + kl * 4) ^ sw));
                ah[mf][2] = *(const uint32_t*)(p0 + ((kbb + 16 + kl * 4) ^ sw));
                ah[mf][3] = *(const uint32_t*)(p1 + ((kbb + 16 + kl * 4) ^ sw));
                am[mf][0] = *(const uint32_t*)(p0 + ((64 + kbb      + kl * 4) ^ sw));
                am[mf][1] = *(const uint32_t*)(p1 + ((64 + kbb      + kl * 4) ^ sw));
                am[mf][2] = *(const uint32_t*)(p0 + ((64 + kbb + 16 + kl * 4) ^ sw));
                am[mf][3] = *(const uint32_t*)(p1 + ((64 + kbb + 16 + kl * 4) ^ sw));
            }
            #pragma unroll
            for (int nf = 0; nf < 8; nf++) {
                const int nr = wn * 64 + nf * 8 + q;
                const uint32_t sw = (uint32_t)((nr & 7) << 4);
                const char* pn = stgB + nr * 128;
                bh[nf][0] = *(const uint32_t*)(pn + ((kbb      + kl * 4) ^ sw));
                bh[nf][1] = *(const uint32_t*)(pn + ((kbb + 16 + kl * 4) ^ sw));
                bm[nf][0] = *(const uint32_t*)(pn + ((64 + kbb      + kl * 4) ^ sw));
                bm[nf][1] = *(const uint32_t*)(pn + ((64 + kbb + 16 + kl * 4) ^ sw));
            }
            #pragma unroll
            for (int mf = 0; mf < 4; mf++)
                #pragma unroll
                for (int nf = 0; nf < 8; nf++) MMA_F16(acc[mf][nf], ah[mf], bh[nf]);
            #pragma unroll
            for (int mf = 0; mf < 4; mf++)
                #pragma unroll
                for (int nf = 0; nf < 8; nf++) MMA_F16(acc[mf][nf], ah[mf], bm[nf]);
            #pragma unroll
            for (int mf = 0; mf < 4; mf++)
                #pragma unroll
                for (int nf = 0; nf < 8; nf++) MMA_F16(acc[mf][nf], am[mf], bh[nf]);
            #pragma unroll
            for (int mf = 0; mf < 4; mf++)
                #pragma unroll
                for (int nf = 0; nf < 8; nf++) MMA_F16(acc[mf][nf], am[mf], bm[nf]);
        }

        // ---- chunk boundary: online softmax/argmin epilogue ---------------
        if ((s & 15) == 15) {
            const int nc = s >> 4;
            #pragma unroll
            for (int mf = 0; mf < 4; mf++) {
                #pragma unroll
                for (int j = 0; j < 2; j++) {
                    const int p    = mf * 2 + j;
                    const int rloc = wm * 64 + mf * 16 + j * 8 + q;
                    const float xn = s_xn[rloc];
                    float d2v[16];
                    float bmn = 3.4e38f; int ba = 0;
                    #pragma unroll
                    for (int nf = 0; nf < 8; nf++) {
                        #pragma unroll
                        for (int t = 0; t < 2; t++) {
                            int col = nc * 256 + wn * 64 + nf * 8 + 2 * kl + t;
                            float d2 = xn + s_cn[col] - 2.f * acc[mf][nf][j * 2 + t];
                            d2v[nf * 2 + t] = d2;
                            if (d2 < bmn || (d2 == bmn && col < ba)) { bmn = d2; ba = col; }
                        }
                    }
                    #pragma unroll
                    for (int o = 1; o <= 2; o <<= 1) {
                        float om = __shfl_xor_sync(0xffffffffu, bmn, o);
                        int   oa = __shfl_xor_sync(0xffffffffu, ba, o);
                        if (om < bmn || (om == bmn && oa < ba)) { bmn = om; ba = oa; }
                    }
                    float le = 0.f, se = 0.f;
                    #pragma unroll
                    for (int v = 0; v < 16; v++) {
                        float w = __expf(bmn - d2v[v]);
                        le += w;
                        se = fmaf(w, d2v[v], se);
                    }
                    #pragma unroll
                    for (int o = 1; o <= 2; o <<= 1) {
                        le += __shfl_xor_sync(0xffffffffu, le, o);
                        se += __shfl_xor_sync(0xffffffffu, se, o);
                    }
                    float newm = fminf(rm[p], bmn);
                    if (bmn < rm[p] || (bmn == rm[p] && ba < ri[p])) ri[p] = ba;
                    float sc_old = __expf(newm - rm[p]);
                    float sc_new = __expf(newm - bmn);
                    rl[p] = rl[p] * sc_old + le * sc_new;
                    rs[p] = rs[p] * sc_old + se * sc_new;
                    rm[p] = newm;
                    #pragma unroll
                    for (int nf = 0; nf < 8; nf++) {
                        acc[mf][nf][j * 2 + 0] = 0.f;
                        acc[mf][nf][j * 2 + 1] = 0.f;
                    }
                }
            }
        }
        __syncthreads();
    }

    // ---- write per-warp partials (one lane per quad) ----------------------
    if (kl == 0) {
        #pragma unroll
        for (int mf = 0; mf < 4; mf++) {
            #pragma unroll
            for (int j = 0; j < 2; j++) {
                int p = mf * 2 + j;
                int rloc = wm * 64 + mf * 16 + j * 8 + q;
                s_pm[wn][rloc] = rm[p];
                s_pl[wn][rloc] = rl[p];
                s_ps[wn][rloc] = rs[p];
                s_pi[wn][rloc] = ri[p];
            }
        }
    }
    __syncthreads();

    // ---- final per-point merge over the 4 N-tile warps --------------------
    if (tid < 128) {
        float m = s_pm[0][tid]; int bi = s_pi[0][tid];
        #pragma unroll
        for (int w = 1; w < 4; w++) {
            float om = s_pm[w][tid]; int oi = s_pi[w][tid];
            if (om < m || (om == m && oi < bi)) { m = om; bi = oi; }
        }
        float l = 0.f, ssum = 0.f;
        #pragma unroll
        for (int w = 0; w < 4; w++) {
            float sc = __expf(m - s_pm[w][tid]);
            l    += s_pl[w][tid] * sc;
            ssum += s_ps[w][tid] * sc;
        }
        int n = row0 + tid;
        out_idx[n] = (float)bi;
        g_ploss[n] = ssum / l;
        s_idx[tid] = bi;
    }
    __syncthreads();

    // ---- fused centroid gather (cluster table L2-resident) ----------------
    for (int i = tid; i < 128 * (DIM / 4); i += 256) {
        int p = i >> 7, c4 = i & 127;
        int ci = s_idx[p];
        float4 v = *reinterpret_cast<const float4*>(crep + (size_t)ci * DIM + c4 * 4);
        *reinterpret_cast<float4*>(out_centroids + (size_t)(row0 + p) * DIM + c4 * 4) = v;
    }
}

// ---------------------------------------------------------------------------
__global__ void loss_reduce_kernel(float* __restrict__ out_loss) {
    __shared__ float sm[1024];
    int tid = threadIdx.x;
    float acc = 0.f;
    for (int i = tid; i < N_PTS; i += 1024) acc += g_ploss[i];
    sm[tid] = acc;
    __syncthreads();
    #pragma unroll
    for (int o = 512; o > 0; o >>= 1) {
        if (tid < o) sm[tid] += sm[tid + o];
        __syncthreads();
    }
    if (tid == 0) out_loss[0] = sm[0] * (1.0f / (float)KCL);
}

// ---------------------------------------------------------------------------
extern "C" void kernel_launch(void* const* d_in, const int* in_sizes, int n_in,
                              void* d_out, int out_size) {
    const float* input = (const float*)d_in[0];   // [N, D]
    const float* crep  = (const float*)d_in[1];   // [K, D]

    float* out           = (float*)d_out;
    float* out_centroids = out;
    float* out_idx       = out + (size_t)N_PTS * DIM;
    float* out_loss      = out + (size_t)N_PTS * DIM + N_PTS;

    __half *Ah, *Al, *Bh, *Bl;
    float *xn, *cn;
    cudaGetSymbolAddress((void**)&Ah, g_Ah);
    cudaGetSymbolAddress((void**)&Al, g_Al);
    cudaGetSymbolAddress((void**)&Bh, g_Bh);
    cudaGetSymbolAddress((void**)&Bl, g_Bl);
    cudaGetSymbolAddress((void**)&xn, g_xnorm);
    cudaGetSymbolAddress((void**)&cn, g_cnorm);

    convert_f16_kernel<<<(N_PTS * 32) / 256, 256>>>(input, Ah, Al, xn, N_PTS);
    convert_f16_kernel<<<(KCL * 32) / 256, 256>>>(crep, Bh, Bl, cn, KCL);

    cudaFuncSetAttribute(dkm_gemm_kernel, cudaFuncAttributeMaxDynamicSharedMemorySize, DSMEM);
    dkm_gemm_kernel<<<N_PTS / 128, 256, DSMEM>>>(crep, out_centroids, out_idx);

    loss_reduce_kernel<<<1, 1024>>>(out_loss);
}

// round 5
// speedup vs baseline: 2.8203x; 1.1668x over previous
#include <cuda_runtime.h>
#include <cuda_fp16.h>
#include <stdint.h>
#include <math.h>

#define N_PTS 32768
#define DIM   512
#define KCL   1024

// ---------------- scratch (static device arrays: allocation-free) ----------
__device__ __half g_Ah[(size_t)N_PTS * DIM];   // 32 MB  fp16 hi
__device__ __half g_Al[(size_t)N_PTS * DIM];   // 32 MB  fp16 lo (residual)
__device__ __half g_Bh[(size_t)KCL * DIM];     // 1 MB
__device__ __half g_Bl[(size_t)KCL * DIM];     // 1 MB
__device__ float g_xnorm[N_PTS];
__device__ float g_cnorm[KCL];
__device__ float g_ploss[N_PTS];

// m16n8k16 fp16 MMA, fp32 accumulate, D=C
#define MMA_F16(d, a, b)                                                        \
    asm volatile(                                                               \
        "mma.sync.aligned.m16n8k16.row.col.f32.f16.f16.f32 "                    \
        "{%0,%1,%2,%3},{%4,%5,%6,%7},{%8,%9},{%0,%1,%2,%3};"                    \
        : "+f"((d)[0]), "+f"((d)[1]), "+f"((d)[2]), "+f"((d)[3])                \
        : "r"((a)[0]), "r"((a)[1]), "r"((a)[2]), "r"((a)[3]),                   \
          "r"((b)[0]), "r"((b)[1]))

#define CP_ASYNC16(dst, src)                                                    \
    asm volatile("cp.async.cg.shared.global [%0], [%1], 16;"                    \
                 :: "r"(dst), "l"(src) : "memory")
#define CP_COMMIT()  asm volatile("cp.async.commit_group;" ::: "memory")
#define CP_WAIT(n)   asm volatile("cp.async.wait_group %0;" :: "n"(n) : "memory")

#define SWZ(x) ((x) ^ (((x) >> 3) & 0x70))

__device__ __forceinline__ uint32_t smem_u32(const void* p) {
    uint32_t a;
    asm("{ .reg .u64 t; cvta.to.shared.u64 t, %1; cvt.u32.u64 %0, t; }" : "=r"(a) : "l"(p));
    return a;
}

// ---------------------------------------------------------------------------
// Convert fp32 rows -> fp16 (hi, lo) split + squared norms. One warp per row.
// ---------------------------------------------------------------------------
__global__ void convert_f16_kernel(const float* __restrict__ x,
                                   __half* __restrict__ hi_arr,
                                   __half* __restrict__ lo_arr,
                                   float* __restrict__ norm_arr,
                                   int nrows) {
    int warp = (blockIdx.x * blockDim.x + threadIdx.x) >> 5;
    int lane = threadIdx.x & 31;
    if (warp >= nrows) return;
    const float* row = x + (size_t)warp * DIM;
    __half* hrow = hi_arr + (size_t)warp * DIM;
    __half* lrow = lo_arr + (size_t)warp * DIM;
    float sq = 0.f;
    #pragma unroll
    for (int i = 0; i < 4; i++) {
        int d = i * 128 + lane * 4;
        float4 v = *reinterpret_cast<const float4*>(row + d);
        float vv[4] = {v.x, v.y, v.z, v.w};
        __half hv[4], lv[4];
        #pragma unroll
        for (int q = 0; q < 4; q++) {
            float val = vv[q];
            sq = fmaf(val, val, sq);
            hv[q] = __float2half_rn(val);
            lv[q] = __float2half_rn(val - __half2float(hv[q]));
        }
        *reinterpret_cast<uint2*>(hrow + d) = *reinterpret_cast<uint2*>(hv);
        *reinterpret_cast<uint2*>(lrow + d) = *reinterpret_cast<uint2*>(lv);
    }
    #pragma unroll
    for (int o = 16; o > 0; o >>= 1) sq += __shfl_xor_sync(0xffffffffu, sq, o);
    if (lane == 0) norm_arr[warp] = sq;
}

// ---------------------------------------------------------------------------
// Main kernel: 3xFP16 mma.sync GEMM (hh+mh+hm) + fused softmax/argmin/gather.
// CTA: 512 threads (16 warps of 32x64), tile M=128, N-chunks of 256 (x4).
// Stage = k32; rows are [hi 64B | lo 64B] = 128B, SW128 swizzled.
// ---------------------------------------------------------------------------
#define STG_A   16384              // 128 rows * 128B
#define STG_B   32768              // 256 rows * 128B
#define STG_SZ  (STG_A + STG_B)    // 49152
#define NSTG    64                 // 4 chunks * 16 k-steps (k32 each)
#define DSMEM   (2 * STG_SZ)       // 98304

__global__ __launch_bounds__(512, 1)
void dkm_gemm_kernel(const float* __restrict__ crep,
                     float* __restrict__ out_centroids,
                     float* __restrict__ out_idx)
{
    extern __shared__ __align__(128) char dsm[];
    __shared__ float s_cn[KCL];
    __shared__ float s_xn[128];
    __shared__ float s_pm[4][128], s_pl[4][128], s_ps[4][128];
    __shared__ int   s_pi[4][128], s_idx[128];

    const int tid  = threadIdx.x;
    const int wid  = tid >> 5;
    const int lane = tid & 31;
    const int q    = lane >> 2;
    const int kl   = lane & 3;
    const int wm   = wid & 3;          // M-tile (0..3) of 32 rows
    const int wn   = wid >> 2;         // N-tile (0..3) of 64 cols
    const int row0 = blockIdx.x * 128;

    for (int i = tid; i < KCL; i += 512) s_cn[i] = g_cnorm[i];
    if (tid < 128) s_xn[tid] = g_xnorm[row0 + tid];
    __syncthreads();

    // ---- stage loader: 3072 x 16B chunks, 6 per thread --------------------
    auto load_stage = [&](int s) {
        const int nc = s >> 4, ks = s & 15;
        const int k0 = ks * 32, c0 = nc * 256;
        const uint32_t base = smem_u32(dsm) + (s & 1) * STG_SZ;
        #pragma unroll
        for (int it = 0; it < 6; it++) {
            int i = it * 512 + tid;
            uint32_t dst; const __half* src;
            if (i < 1024) {                       // A: 128 rows x 8 chunks
                int r = i >> 3, c = i & 7;
                src = (c < 4 ? g_Ah + (size_t)(row0 + r) * DIM + k0 + c * 8
                             : g_Al + (size_t)(row0 + r) * DIM + k0 + (c - 4) * 8);
                dst = base + SWZ((uint32_t)(r * 128 + c * 16));
            } else {                              // B: 256 rows x 8 chunks
                int j = i - 1024, r = j >> 3, c = j & 7;
                src = (c < 4 ? g_Bh + (size_t)(c0 + r) * DIM + k0 + c * 8
                             : g_Bl + (size_t)(c0 + r) * DIM + k0 + (c - 4) * 8);
                dst = base + STG_A + SWZ((uint32_t)(r * 128 + c * 16));
            }
            CP_ASYNC16(dst, (const void*)src);
        }
        CP_COMMIT();
    };

    // ---- per-point running softmax state (4 points per lane) --------------
    float rm[4], rl[4], rs[4];
    int   ri[4];
    #pragma unroll
    for (int p = 0; p < 4; p++) { rm[p] = 3.4e38f; rl[p] = 0.f; rs[p] = 0.f; ri[p] = 0; }

    float acc[2][8][4];
    #pragma unroll
    for (int mf = 0; mf < 2; mf++)
        #pragma unroll
        for (int nf = 0; nf < 8; nf++)
            #pragma unroll
            for (int t = 0; t < 4; t++) acc[mf][nf][t] = 0.f;

    load_stage(0);

    for (int s = 0; s < NSTG; s++) {
        if (s + 1 < NSTG) load_stage(s + 1);
        if (s + 1 < NSTG) { CP_WAIT(1); } else { CP_WAIT(0); }
        __syncthreads();

        const char* stgA = dsm + (s & 1) * STG_SZ;
        const char* stgB = stgA + STG_A;

        #pragma unroll
        for (int kb = 0; kb < 2; kb++) {           // two k16 steps per stage
            const uint32_t kbb = kb * 32;          // byte offset of k16 block
            uint32_t ah[2][4], am[2][4], bb[8][2];
            #pragma unroll
            for (int mf = 0; mf < 2; mf++) {
                const int r = wm * 32 + mf * 16 + q;
                const uint32_t sw = (uint32_t)((r & 7) << 4);
                const char* p0 = stgA + r * 128;
                const char* p1 = stgA + (r + 8) * 128;
                ah[mf][0] = *(const uint32_t*)(p0 + ((kbb      + kl * 4) ^ sw));
                ah[mf][1] = *(const uint32_t*)(p1 + ((kbb      + kl * 4) ^ sw));
                ah[mf][2] = *(const uint32_t*)(p0 + ((kbb + 16 + kl * 4) ^ sw));
                ah[mf][3] = *(const uint32_t*)(p1 + ((kbb + 16 + kl * 4) ^ sw));
                am[mf][0] = *(const uint32_t*)(p0 + ((64 + kbb      + kl * 4) ^ sw));
                am[mf][1] = *(const uint32_t*)(p1 + ((64 + kbb      + kl * 4) ^ sw));
                am[mf][2] = *(const uint32_t*)(p0 + ((64 + kbb + 16 + kl * 4) ^ sw));
                am[mf][3] = *(const uint32_t*)(p1 + ((64 + kbb + 16 + kl * 4) ^ sw));
            }
            // B hi fragments -> passes hh and mh
            #pragma unroll
            for (int nf = 0; nf < 8; nf++) {
                const int nr = wn * 64 + nf * 8 + q;
                const uint32_t sw = (uint32_t)((nr & 7) << 4);
                const char* pn = stgB + nr * 128;
                bb[nf][0] = *(const uint32_t*)(pn + ((kbb      + kl * 4) ^ sw));
                bb[nf][1] = *(const uint32_t*)(pn + ((kbb + 16 + kl * 4) ^ sw));
            }
            #pragma unroll
            for (int mf = 0; mf < 2; mf++)
                #pragma unroll
                for (int nf = 0; nf < 8; nf++) MMA_F16(acc[mf][nf], ah[mf], bb[nf]);
            #pragma unroll
            for (int mf = 0; mf < 2; mf++)
                #pragma unroll
                for (int nf = 0; nf < 8; nf++) MMA_F16(acc[mf][nf], am[mf], bb[nf]);
            // B lo fragments -> pass hm
            #pragma unroll
            for (int nf = 0; nf < 8; nf++) {
                const int nr = wn * 64 + nf * 8 + q;
                const uint32_t sw = (uint32_t)((nr & 7) << 4);
                const char* pn = stgB + nr * 128;
                bb[nf][0] = *(const uint32_t*)(pn + ((64 + kbb      + kl * 4) ^ sw));
                bb[nf][1] = *(const uint32_t*)(pn + ((64 + kbb + 16 + kl * 4) ^ sw));
            }
            #pragma unroll
            for (int mf = 0; mf < 2; mf++)
                #pragma unroll
                for (int nf = 0; nf < 8; nf++) MMA_F16(acc[mf][nf], ah[mf], bb[nf]);
        }

        // ---- chunk boundary: online softmax/argmin epilogue ---------------
        if ((s & 15) == 15) {
            const int nc = s >> 4;
            #pragma unroll
            for (int mf = 0; mf < 2; mf++) {
                #pragma unroll
                for (int j = 0; j < 2; j++) {
                    const int p    = mf * 2 + j;
                    const int rloc = wm * 32 + mf * 16 + j * 8 + q;
                    const float xn = s_xn[rloc];
                    float d2v[16];
                    float bmn = 3.4e38f; int ba = 0;
                    #pragma unroll
                    for (int nf = 0; nf < 8; nf++) {
                        #pragma unroll
                        for (int t = 0; t < 2; t++) {
                            int col = nc * 256 + wn * 64 + nf * 8 + 2 * kl + t;
                            float d2 = xn + s_cn[col] - 2.f * acc[mf][nf][j * 2 + t];
                            d2v[nf * 2 + t] = d2;
                            if (d2 < bmn || (d2 == bmn && col < ba)) { bmn = d2; ba = col; }
                        }
                    }
                    #pragma unroll
                    for (int o = 1; o <= 2; o <<= 1) {
                        float om = __shfl_xor_sync(0xffffffffu, bmn, o);
                        int   oa = __shfl_xor_sync(0xffffffffu, ba, o);
                        if (om < bmn || (om == bmn && oa < ba)) { bmn = om; ba = oa; }
                    }
                    float le = 0.f, se = 0.f;
                    #pragma unroll
                    for (int v = 0; v < 16; v++) {
                        float w = __expf(bmn - d2v[v]);
                        le += w;
                        se = fmaf(w, d2v[v], se);
                    }
                    #pragma unroll
                    for (int o = 1; o <= 2; o <<= 1) {
                        le += __shfl_xor_sync(0xffffffffu, le, o);
                        se += __shfl_xor_sync(0xffffffffu, se, o);
                    }
                    float newm = fminf(rm[p], bmn);
                    if (bmn < rm[p] || (bmn == rm[p] && ba < ri[p])) ri[p] = ba;
                    float sc_old = __expf(newm - rm[p]);
                    float sc_new = __expf(newm - bmn);
                    rl[p] = rl[p] * sc_old + le * sc_new;
                    rs[p] = rs[p] * sc_old + se * sc_new;
                    rm[p] = newm;
                    #pragma unroll
                    for (int nf = 0; nf < 8; nf++) {
                        acc[mf][nf][j * 2 + 0] = 0.f;
                        acc[mf][nf][j * 2 + 1] = 0.f;
                    }
                }
            }
        }
        __syncthreads();
    }

    // ---- write per-warp partials (one lane per quad) ----------------------
    if (kl == 0) {
        #pragma unroll
        for (int mf = 0; mf < 2; mf++) {
            #pragma unroll
            for (int j = 0; j < 2; j++) {
                int p = mf * 2 + j;
                int rloc = wm * 32 + mf * 16 + j * 8 + q;
                s_pm[wn][rloc] = rm[p];
                s_pl[wn][rloc] = rl[p];
                s_ps[wn][rloc] = rs[p];
                s_pi[wn][rloc] = ri[p];
            }
        }
    }
    __syncthreads();

    // ---- final per-point merge over the 4 N-tile warp groups --------------
    if (tid < 128) {
        float m = s_pm[0][tid]; int bi = s_pi[0][tid];
        #pragma unroll
        for (int w = 1; w < 4; w++) {
            float om = s_pm[w][tid]; int oi = s_pi[w][tid];
            if (om < m || (om == m && oi < bi)) { m = om; bi = oi; }
        }
        float l = 0.f, ssum = 0.f;
        #pragma unroll
        for (int w = 0; w < 4; w++) {
            float sc = __expf(m - s_pm[w][tid]);
            l    += s_pl[w][tid] * sc;
            ssum += s_ps[w][tid] * sc;
        }
        int n = row0 + tid;
        out_idx[n] = (float)bi;
        g_ploss[n] = ssum / l;
        s_idx[tid] = bi;
    }
    __syncthreads();

    // ---- fused centroid gather (cluster table L2-resident) ----------------
    for (int i = tid; i < 128 * (DIM / 4); i += 512) {
        int p = i >> 7, c4 = i & 127;
        int ci = s_idx[p];
        float4 v = *reinterpret_cast<const float4*>(crep + (size_t)ci * DIM + c4 * 4);
        *reinterpret_cast<float4*>(out_centroids + (size_t)(row0 + p) * DIM + c4 * 4) = v;
    }
}

// ---------------------------------------------------------------------------
__global__ void loss_reduce_kernel(float* __restrict__ out_loss) {
    __shared__ float sm[1024];
    int tid = threadIdx.x;
    float acc = 0.f;
    for (int i = tid; i < N_PTS; i += 1024) acc += g_ploss[i];
    sm[tid] = acc;
    __syncthreads();
    #pragma unroll
    for (int o = 512; o > 0; o >>= 1) {
        if (tid < o) sm[tid] += sm[tid + o];
        __syncthreads();
    }
    if (tid == 0) out_loss[0] = sm[0] * (1.0f / (float)KCL);
}

// ---------------------------------------------------------------------------
extern "C" void kernel_launch(void* const* d_in, const int* in_sizes, int n_in,
                              void* d_out, int out_size) {
    const float* input = (const float*)d_in[0];   // [N, D]
    const float* crep  = (const float*)d_in[1];   // [K, D]

    float* out           = (float*)d_out;
    float* out_centroids = out;
    float* out_idx       = out + (size_t)N_PTS * DIM;
    float* out_loss      = out + (size_t)N_PTS * DIM + N_PTS;

    __half *Ah, *Al, *Bh, *Bl;
    float *xn, *cn;
    cudaGetSymbolAddress((void**)&Ah, g_Ah);
    cudaGetSymbolAddress((void**)&Al, g_Al);
    cudaGetSymbolAddress((void**)&Bh, g_Bh);
    cudaGetSymbolAddress((void**)&Bl, g_Bl);
    cudaGetSymbolAddress((void**)&xn, g_xnorm);
    cudaGetSymbolAddress((void**)&cn, g_cnorm);

    convert_f16_kernel<<<(N_PTS * 32) / 256, 256>>>(input, Ah, Al, xn, N_PTS);
    convert_f16_kernel<<<(KCL * 32) / 256, 256>>>(crep, Bh, Bl, cn, KCL);

    cudaFuncSetAttribute(dkm_gemm_kernel, cudaFuncAttributeMaxDynamicSharedMemorySize, DSMEM);
    dkm_gemm_kernel<<<N_PTS / 128, 512, DSMEM>>>(crep, out_centroids, out_idx);

    loss_reduce_kernel<<<1, 1024>>>(out_loss);
}

// round 6
// speedup vs baseline: 2.9507x; 1.0462x over previous
#include <cuda_runtime.h>
#include <cuda_fp16.h>
#include <stdint.h>
#include <math.h>

#define N_PTS 32768
#define DIM   512
#define KCL   1024

// ---------------- scratch (static device arrays: allocation-free) ----------
__device__ __half g_Ah[(size_t)N_PTS * DIM];   // 32 MB  fp16 hi
__device__ __half g_Al[(size_t)N_PTS * DIM];   // 32 MB  fp16 lo (residual)
__device__ __half g_Bh[(size_t)KCL * DIM];     // 1 MB
__device__ __half g_Bl[(size_t)KCL * DIM];     // 1 MB
__device__ float g_xnorm[N_PTS];
__device__ float g_cnorm[KCL];
__device__ float g_ploss[N_PTS];

// m16n8k16 fp16 MMA, fp32 accumulate, D=C
#define MMA_F16(d, a, b)                                                        \
    asm volatile(                                                               \
        "mma.sync.aligned.m16n8k16.row.col.f32.f16.f16.f32 "                    \
        "{%0,%1,%2,%3},{%4,%5,%6,%7},{%8,%9},{%0,%1,%2,%3};"                    \
        : "+f"((d)[0]), "+f"((d)[1]), "+f"((d)[2]), "+f"((d)[3])                \
        : "r"((a)[0]), "r"((a)[1]), "r"((a)[2]), "r"((a)[3]),                   \
          "r"((b)[0]), "r"((b)[1]))

#define LDMX4(r0, r1, r2, r3, addr)                                             \
    asm volatile("ldmatrix.sync.aligned.m8n8.x4.shared.b16 {%0,%1,%2,%3}, [%4];"\
                 : "=r"(r0), "=r"(r1), "=r"(r2), "=r"(r3) : "r"(addr))

#define CP_ASYNC16(dst, src)                                                    \
    asm volatile("cp.async.cg.shared.global [%0], [%1], 16;"                    \
                 :: "r"(dst), "l"(src) : "memory")
#define CP_COMMIT()  asm volatile("cp.async.commit_group;" ::: "memory")
#define CP_WAIT(n)   asm volatile("cp.async.wait_group %0;" :: "n"(n) : "memory")

#define SWZ(x) ((x) ^ (((x) >> 3) & 0x70))

__device__ __forceinline__ uint32_t smem_u32(const void* p) {
    uint32_t a;
    asm("{ .reg .u64 t; cvta.to.shared.u64 t, %1; cvt.u32.u64 %0, t; }" : "=r"(a) : "l"(p));
    return a;
}

// ---------------------------------------------------------------------------
// Convert fp32 rows -> fp16 (hi, lo) split + squared norms. One warp per row.
// ---------------------------------------------------------------------------
__global__ void convert_f16_kernel(const float* __restrict__ x,
                                   __half* __restrict__ hi_arr,
                                   __half* __restrict__ lo_arr,
                                   float* __restrict__ norm_arr,
                                   int nrows) {
    int warp = (blockIdx.x * blockDim.x + threadIdx.x) >> 5;
    int lane = threadIdx.x & 31;
    if (warp >= nrows) return;
    const float* row = x + (size_t)warp * DIM;
    __half* hrow = hi_arr + (size_t)warp * DIM;
    __half* lrow = lo_arr + (size_t)warp * DIM;
    float sq = 0.f;
    #pragma unroll
    for (int i = 0; i < 4; i++) {
        int d = i * 128 + lane * 4;
        float4 v = *reinterpret_cast<const float4*>(row + d);
        float vv[4] = {v.x, v.y, v.z, v.w};
        __half hv[4], lv[4];
        #pragma unroll
        for (int q = 0; q < 4; q++) {
            float val = vv[q];
            sq = fmaf(val, val, sq);
            hv[q] = __float2half_rn(val);
            lv[q] = __float2half_rn(val - __half2float(hv[q]));
        }
        *reinterpret_cast<uint2*>(hrow + d) = *reinterpret_cast<uint2*>(hv);
        *reinterpret_cast<uint2*>(lrow + d) = *reinterpret_cast<uint2*>(lv);
    }
    #pragma unroll
    for (int o = 16; o > 0; o >>= 1) sq += __shfl_xor_sync(0xffffffffu, sq, o);
    if (lane == 0) norm_arr[warp] = sq;
}

// ---------------------------------------------------------------------------
// Main kernel: 3xFP16 mma.sync GEMM (hh+mh+hm) + fused softmax/argmin/gather.
// CTA: 512 threads (16 warps of 32x64), tile M=128, N-chunks of 256 (x4).
// 3-stage cp.async pipeline, one __syncthreads per stage, ldmatrix fragments.
// Stage = k32; rows are [hi 64B | lo 64B] = 128B, SW128 swizzled.
// ---------------------------------------------------------------------------
#define STG_A   16384              // 128 rows * 128B
#define STG_B   32768              // 256 rows * 128B
#define STG_SZ  (STG_A + STG_B)    // 49152
#define NSTG    64                 // 4 chunks * 16 k-steps (k32 each)
#define DSMEM   (3 * STG_SZ)       // 147456

__global__ __launch_bounds__(512, 1)
void dkm_gemm_kernel(const float* __restrict__ crep,
                     float* __restrict__ out_centroids,
                     float* __restrict__ out_idx)
{
    extern __shared__ __align__(128) char dsm[];
    __shared__ float s_cn[KCL];
    __shared__ float s_xn[128];
    __shared__ float s_pm[4][128], s_pl[4][128], s_ps[4][128];
    __shared__ int   s_pi[4][128], s_idx[128];

    const int tid  = threadIdx.x;
    const int wid  = tid >> 5;
    const int lane = tid & 31;
    const int q    = lane >> 2;
    const int kl   = lane & 3;
    const int g    = lane >> 3;        // ldmatrix address group
    const int lr   = lane & 7;
    const int wm   = wid & 3;          // M-tile (0..3) of 32 rows
    const int wn   = wid >> 2;         // N-tile (0..3) of 64 cols
    const int row0 = blockIdx.x * 128;
    const uint32_t dsmu = smem_u32(dsm);

    for (int i = tid; i < KCL; i += 512) s_cn[i] = g_cnorm[i];
    if (tid < 128) s_xn[tid] = g_xnorm[row0 + tid];
    __syncthreads();

    // ---- per-lane ldmatrix offsets (stage-independent) --------------------
    uint32_t offA[2], offB[4];
    #pragma unroll
    for (int mf = 0; mf < 2; mf++) {
        int r = wm * 32 + mf * 16 + (g & 1) * 8 + lr;
        offA[mf] = (uint32_t)(r * 128) + ((uint32_t)((g >> 1) * 16) ^ ((uint32_t)(r & 7) << 4));
    }
    #pragma unroll
    for (int t = 0; t < 4; t++) {
        int r = wn * 64 + t * 16 + (g >= 2 ? 8 : 0) + lr;
        offB[t] = (uint32_t)(r * 128) + ((uint32_t)((g & 1) * 16) ^ ((uint32_t)(r & 7) << 4));
    }

    // ---- stage loader: 3072 x 16B chunks, 6 per thread --------------------
    auto load_stage = [&](int s) {
        const int nc = s >> 4, ks = s & 15;
        const int k0 = ks * 32, c0 = nc * 256;
        const uint32_t base = dsmu + (s % 3) * STG_SZ;
        #pragma unroll
        for (int it = 0; it < 6; it++) {
            int i = it * 512 + tid;
            uint32_t dst; const __half* src;
            if (i < 1024) {                       // A: 128 rows x 8 chunks
                int r = i >> 3, c = i & 7;
                src = (c < 4 ? g_Ah + (size_t)(row0 + r) * DIM + k0 + c * 8
                             : g_Al + (size_t)(row0 + r) * DIM + k0 + (c - 4) * 8);
                dst = base + SWZ((uint32_t)(r * 128 + c * 16));
            } else {                              // B: 256 rows x 8 chunks
                int j = i - 1024, r = j >> 3, c = j & 7;
                src = (c < 4 ? g_Bh + (size_t)(c0 + r) * DIM + k0 + c * 8
                             : g_Bl + (size_t)(c0 + r) * DIM + k0 + (c - 4) * 8);
                dst = base + STG_A + SWZ((uint32_t)(r * 128 + c * 16));
            }
            CP_ASYNC16(dst, (const void*)src);
        }
        CP_COMMIT();
    };

    // ---- per-point running softmax state (4 points per lane) --------------
    float rm[4], rl[4], rs[4];
    int   ri[4];
    #pragma unroll
    for (int p = 0; p < 4; p++) { rm[p] = 3.4e38f; rl[p] = 0.f; rs[p] = 0.f; ri[p] = 0; }

    float acc[2][8][4];
    #pragma unroll
    for (int mf = 0; mf < 2; mf++)
        #pragma unroll
        for (int nf = 0; nf < 8; nf++)
            #pragma unroll
            for (int t = 0; t < 4; t++) acc[mf][nf][t] = 0.f;

    load_stage(0);
    load_stage(1);

    for (int s = 0; s < NSTG; s++) {
        if (s < NSTG - 2) { CP_WAIT(1); } else { CP_WAIT(0); }
        __syncthreads();
        if (s + 2 < NSTG) load_stage(s + 2);   // overlaps with compute below

        const uint32_t abase = dsmu + (s % 3) * STG_SZ;
        const uint32_t bbase = abase + STG_A;

        #pragma unroll
        for (int kb = 0; kb < 2; kb++) {           // two k16 steps per stage
            const uint32_t kx = (uint32_t)kb << 5;
            uint32_t ah[2][4], am[2][4], bb[4][4];
            #pragma unroll
            for (int mf = 0; mf < 2; mf++) {
                const uint32_t aH = abase + (offA[mf] ^ kx);
                LDMX4(ah[mf][0], ah[mf][1], ah[mf][2], ah[mf][3], aH);
                LDMX4(am[mf][0], am[mf][1], am[mf][2], am[mf][3], aH ^ 64u);
            }
            // B hi fragments -> passes hh and mh
            #pragma unroll
            for (int t = 0; t < 4; t++)
                LDMX4(bb[t][0], bb[t][1], bb[t][2], bb[t][3], bbase + (offB[t] ^ kx));
            #pragma unroll
            for (int mf = 0; mf < 2; mf++)
                #pragma unroll
                for (int t = 0; t < 4; t++) {
                    MMA_F16(acc[mf][2 * t],     ah[mf], (bb[t] + 0));
                    MMA_F16(acc[mf][2 * t + 1], ah[mf], (bb[t] + 2));
                }
            #pragma unroll
            for (int mf = 0; mf < 2; mf++)
                #pragma unroll
                for (int t = 0; t < 4; t++) {
                    MMA_F16(acc[mf][2 * t],     am[mf], (bb[t] + 0));
                    MMA_F16(acc[mf][2 * t + 1], am[mf], (bb[t] + 2));
                }
            // B lo fragments -> pass hm
            #pragma unroll
            for (int t = 0; t < 4; t++)
                LDMX4(bb[t][0], bb[t][1], bb[t][2], bb[t][3], bbase + ((offB[t] ^ kx) ^ 64u));
            #pragma unroll
            for (int mf = 0; mf < 2; mf++)
                #pragma unroll
                for (int t = 0; t < 4; t++) {
                    MMA_F16(acc[mf][2 * t],     ah[mf], (bb[t] + 0));
                    MMA_F16(acc[mf][2 * t + 1], ah[mf], (bb[t] + 2));
                }
        }

        // ---- chunk boundary: online softmax/argmin epilogue ---------------
        if ((s & 15) == 15) {
            const int nc = s >> 4;
            #pragma unroll
            for (int mf = 0; mf < 2; mf++) {
                #pragma unroll
                for (int j = 0; j < 2; j++) {
                    const int p    = mf * 2 + j;
                    const int rloc = wm * 32 + mf * 16 + j * 8 + q;
                    const float xn = s_xn[rloc];
                    float d2v[16];
                    float bmn = 3.4e38f; int ba = 0;
                    #pragma unroll
                    for (int nf = 0; nf < 8; nf++) {
                        #pragma unroll
                        for (int t = 0; t < 2; t++) {
                            int col = nc * 256 + wn * 64 + nf * 8 + 2 * kl + t;
                            float d2 = xn + s_cn[col] - 2.f * acc[mf][nf][j * 2 + t];
                            d2v[nf * 2 + t] = d2;
                            if (d2 < bmn || (d2 == bmn && col < ba)) { bmn = d2; ba = col; }
                        }
                    }
                    #pragma unroll
                    for (int o = 1; o <= 2; o <<= 1) {
                        float om = __shfl_xor_sync(0xffffffffu, bmn, o);
                        int   oa = __shfl_xor_sync(0xffffffffu, ba, o);
                        if (om < bmn || (om == bmn && oa < ba)) { bmn = om; ba = oa; }
                    }
                    float le = 0.f, se = 0.f;
                    #pragma unroll
                    for (int v = 0; v < 16; v++) {
                        float w = __expf(bmn - d2v[v]);
                        le += w;
                        se = fmaf(w, d2v[v], se);
                    }
                    #pragma unroll
                    for (int o = 1; o <= 2; o <<= 1) {
                        le += __shfl_xor_sync(0xffffffffu, le, o);
                        se += __shfl_xor_sync(0xffffffffu, se, o);
                    }
                    float newm = fminf(rm[p], bmn);
                    if (bmn < rm[p] || (bmn == rm[p] && ba < ri[p])) ri[p] = ba;
                    float sc_old = __expf(newm - rm[p]);
                    float sc_new = __expf(newm - bmn);
                    rl[p] = rl[p] * sc_old + le * sc_new;
                    rs[p] = rs[p] * sc_old + se * sc_new;
                    rm[p] = newm;
                    #pragma unroll
                    for (int nf = 0; nf < 8; nf++) {
                        acc[mf][nf][j * 2 + 0] = 0.f;
                        acc[mf][nf][j * 2 + 1] = 0.f;
                    }
                }
            }
        }
    }

    // ---- write per-warp partials (one lane per quad) ----------------------
    if (kl == 0) {
        #pragma unroll
        for (int mf = 0; mf < 2; mf++) {
            #pragma unroll
            for (int j = 0; j < 2; j++) {
                int p = mf * 2 + j;
                int rloc = wm * 32 + mf * 16 + j * 8 + q;
                s_pm[wn][rloc] = rm[p];
                s_pl[wn][rloc] = rl[p];
                s_ps[wn][rloc] = rs[p];
                s_pi[wn][rloc] = ri[p];
            }
        }
    }
    __syncthreads();

    // ---- final per-point merge over the 4 N-tile warp groups --------------
    if (tid < 128) {
        float m = s_pm[0][tid]; int bi = s_pi[0][tid];
        #pragma unroll
        for (int w = 1; w < 4; w++) {
            float om = s_pm[w][tid]; int oi = s_pi[w][tid];
            if (om < m || (om == m && oi < bi)) { m = om; bi = oi; }
        }
        float l = 0.f, ssum = 0.f;
        #pragma unroll
        for (int w = 0; w < 4; w++) {
            float sc = __expf(m - s_pm[w][tid]);
            l    += s_pl[w][tid] * sc;
            ssum += s_ps[w][tid] * sc;
        }
        int n = row0 + tid;
        out_idx[n] = (float)bi;
        g_ploss[n] = ssum / l;
        s_idx[tid] = bi;
    }
    __syncthreads();

    // ---- fused centroid gather (cluster table L2-resident) ----------------
    for (int i = tid; i < 128 * (DIM / 4); i += 512) {
        int p = i >> 7, c4 = i & 127;
        int ci = s_idx[p];
        float4 v = *reinterpret_cast<const float4*>(crep + (size_t)ci * DIM + c4 * 4);
        *reinterpret_cast<float4*>(out_centroids + (size_t)(row0 + p) * DIM + c4 * 4) = v;
    }
}

// ---------------------------------------------------------------------------
__global__ void loss_reduce_kernel(float* __restrict__ out_loss) {
    __shared__ float sm[1024];
    int tid = threadIdx.x;
    float acc = 0.f;
    for (int i = tid; i < N_PTS; i += 1024) acc += g_ploss[i];
    sm[tid] = acc;
    __syncthreads();
    #pragma unroll
    for (int o = 512; o > 0; o >>= 1) {
        if (tid < o) sm[tid] += sm[tid + o];
        __syncthreads();
    }
    if (tid == 0) out_loss[0] = sm[0] * (1.0f / (float)KCL);
}

// ---------------------------------------------------------------------------
extern "C" void kernel_launch(void* const* d_in, const int* in_sizes, int n_in,
                              void* d_out, int out_size) {
    const float* input = (const float*)d_in[0];   // [N, D]
    const float* crep  = (const float*)d_in[1];   // [K, D]

    float* out           = (float*)d_out;
    float* out_centroids = out;
    float* out_idx       = out + (size_t)N_PTS * DIM;
    float* out_loss      = out + (size_t)N_PTS * DIM + N_PTS;

    __half *Ah, *Al, *Bh, *Bl;
    float *xn, *cn;
    cudaGetSymbolAddress((void**)&Ah, g_Ah);
    cudaGetSymbolAddress((void**)&Al, g_Al);
    cudaGetSymbolAddress((void**)&Bh, g_Bh);
    cudaGetSymbolAddress((void**)&Bl, g_Bl);
    cudaGetSymbolAddress((void**)&xn, g_xnorm);
    cudaGetSymbolAddress((void**)&cn, g_cnorm);

    convert_f16_kernel<<<(N_PTS * 32) / 256, 256>>>(input, Ah, Al, xn, N_PTS);
    convert_f16_kernel<<<(KCL * 32) / 256, 256>>>(crep, Bh, Bl, cn, KCL);

    cudaFuncSetAttribute(dkm_gemm_kernel, cudaFuncAttributeMaxDynamicSharedMemorySize, DSMEM);
    dkm_gemm_kernel<<<N_PTS / 128, 512, DSMEM>>>(crep, out_centroids, out_idx);

    loss_reduce_kernel<<<1, 1024>>>(out_loss);
}